// round 16
// baseline (speedup 1.0000x reference)
#include <cuda_runtime.h>

#define DD     4096
#define KB     128
#define TROWS  16384

__device__ int            g_offsets[KB + 1];
__device__ unsigned short g_perm[DD];
__device__ float4         g_Yt[(TROWS / 4) * KB];   // [t/4][k] = y rows t..t+3

// staging stride 8: j=8t+q -> swz low3 = q ^ (t&7): conflict-free
__device__ __forceinline__ int swz(int j) { return j ^ ((j >> 3) & 7); }

__device__ __forceinline__ void fma2(unsigned long long& d,
                                     unsigned long long a, unsigned long long b) {
    asm("fma.rn.f32x2 %0, %1, %2, %0;" : "+l"(d) : "l"(a), "l"(b));
}
__device__ __forceinline__ unsigned long long pack2(float q) {
    unsigned long long r;
    asm("mov.b64 %0, {%1, %1};" : "=l"(r) : "r"(__float_as_uint(q)));
    return r;
}
__device__ __forceinline__ float lo2(unsigned long long v) {
    return __uint_as_float((unsigned)v);
}
__device__ __forceinline__ float hi2(unsigned long long v) {
    return __uint_as_float((unsigned)(v >> 32));
}

// ---------------------------------------------------------------------------
// k0: 128 blocks x 32 thr. Block b builds bin b's CSR segment, then reorders
// the segment round-robin over bank-groups (swz(j)&7, cycle rotated 4 for odd
// bins) so k1's gather phases hit distinct bank-groups. Fallback = unordered.
// ---------------------------------------------------------------------------
__global__ void k0_build(const int* __restrict__ assign) {
    __shared__ unsigned short s_list[1024];
    __shared__ unsigned short s_buck[8][128];
    __shared__ int s_cntg[8];
    __shared__ int s_n;
    const int b = blockIdx.x, lane = threadIdx.x;

    int below = 0;
    for (int i = 0; i < DD / 32; i++) {
        int a = assign[i * 32 + lane] & 127;
        below += (a < b);
    }
    #pragma unroll
    for (int d = 16; d >= 1; d >>= 1)
        below += __shfl_xor_sync(0xffffffffu, below, d);
    const int base0 = below;

    if (lane == 0) {
        g_offsets[b] = base0;
        if (b == KB - 1) g_offsets[KB] = DD;
    }

    // pass 1: unordered CSR (fallback content) + smem copy
    int e = 0;
    for (int i = 0; i < DD / 32; i++) {
        int j = i * 32 + lane;
        bool hit = ((assign[j] & 127) == b);
        unsigned m = __ballot_sync(0xffffffffu, hit);
        if (hit) {
            int er = e + __popc(m & ((1u << lane) - 1u));
            g_perm[base0 + er] = (unsigned short)j;
            if (er < 1024) s_list[er] = (unsigned short)j;
        }
        e += __popc(m);
    }
    if (lane == 0) s_n = e;
    __syncwarp();
    const int n = s_n;
    if (n > 1024) return;   // keep unordered fallback

    // bucket by bank-group (lane g handles group g; stable in entry order)
    if (lane < 8) {
        int c = 0;
        for (int i = 0; i < n; i++) {
            int j = (int)s_list[i];
            if ((swz(j) & 7) == lane && c < 128)
                s_buck[lane][c++] = (unsigned short)j;
        }
        s_cntg[lane] = c;
    }
    __syncwarp();

    // verify no bucket overflow (else positions wouldn't be a permutation)
    int total = 0;
    #pragma unroll
    for (int g = 0; g < 8; g++) total += s_cntg[g];
    if (total != n) return;   // keep unordered fallback

    // emit round-robin, cycle rotated by 4 for odd bins
    if (lane < 8) {
        const int g = lane;
        const int rot = (b & 1) * 4;
        const int ordg = (g - rot) & 7;
        const int cg = s_cntg[g];
        for (int r = 0; r < cg; r++) {
            int pos = 0;
            #pragma unroll
            for (int g2 = 0; g2 < 8; g2++) {
                int c2 = s_cntg[g2];
                int ord2 = (g2 - rot) & 7;
                pos += (c2 < r ? c2 : r);
                pos += (ord2 < ordg && c2 > r) ? 1 : 0;
            }
            g_perm[base0 + pos] = s_buck[g][r];
        }
    }
}

// ---------------------------------------------------------------------------
// K1 (R15 version, byte-identical): 512 thr, 2 CTA/SM, 16 rows/CTA.
// ---------------------------------------------------------------------------
#define K1_OFF_PERM 65536
#define K1_OFF_OFFS (K1_OFF_PERM + 8192)
#define K1_SMEM     (K1_OFF_OFFS + 4 * (KB + 1))

__global__ void __launch_bounds__(512, 2)
k1_bins(const float* __restrict__ x) {
    extern __shared__ char smem[];
    float4*         s_x4   = (float4*)smem;                         // 64 KB
    unsigned short* s_perm = (unsigned short*)(smem + K1_OFF_PERM); // pre-swz byte offs
    int*            s_off  = (int*)(smem + K1_OFF_OFFS);

    const int tid = threadIdx.x;

    for (int i = tid; i < DD / 2; i += 512) {
        unsigned pr = ((const unsigned*)g_perm)[i];
        unsigned o0 = (unsigned)(swz((int)(pr & 0xffffu)) << 4);
        unsigned o1 = (unsigned)(swz((int)(pr >> 16)) << 4);
        ((unsigned*)s_perm)[i] = o0 | (o1 << 16);
    }
    if (tid <= KB) s_off[tid] = g_offsets[tid];

    const int bin = tid >> 2, sub = tid & 3;
    const float4* x4 = (const float4*)x;
    const int t0 = blockIdx.x * 16;

    float4 v[4][2];
    #pragma unroll
    for (int r = 0; r < 4; r++) {
        v[r][0] = x4[(size_t)(t0 + r) * 1024 + 2 * tid];
        v[r][1] = x4[(size_t)(t0 + r) * 1024 + 2 * tid + 1];
    }

    __syncthreads();
    const int lo = s_off[bin] + sub, hi = s_off[bin + 1];

    #pragma unroll 1
    for (int b = 0; b < 4; b++) {
        const int tb = t0 + 4 * b;

        #pragma unroll
        for (int p = 0; p < 2; p++) {
            s_x4[swz(8 * tid + 4 * p + 0)] = make_float4(v[0][p].x, v[1][p].x, v[2][p].x, v[3][p].x);
            s_x4[swz(8 * tid + 4 * p + 1)] = make_float4(v[0][p].y, v[1][p].y, v[2][p].y, v[3][p].y);
            s_x4[swz(8 * tid + 4 * p + 2)] = make_float4(v[0][p].z, v[1][p].z, v[2][p].z, v[3][p].z);
            s_x4[swz(8 * tid + 4 * p + 3)] = make_float4(v[0][p].w, v[1][p].w, v[2][p].w, v[3][p].w);
        }
        __syncthreads();

        if (b < 3) {
            #pragma unroll
            for (int r = 0; r < 4; r++) {
                v[r][0] = x4[(size_t)(tb + 4 + r) * 1024 + 2 * tid];
                v[r][1] = x4[(size_t)(tb + 4 + r) * 1024 + 2 * tid + 1];
            }
        }

        float4 acc = make_float4(0.f, 0.f, 0.f, 0.f);
        const char* bx = (const char*)s_x4;
        for (int s = lo; s < hi; s += 4) {
            float4 xv = *(const float4*)(bx + s_perm[s]);
            acc.x += xv.x; acc.y += xv.y; acc.z += xv.z; acc.w += xv.w;
        }
        #pragma unroll
        for (int d = 2; d >= 1; d >>= 1) {
            acc.x += __shfl_down_sync(0xffffffffu, acc.x, d);
            acc.y += __shfl_down_sync(0xffffffffu, acc.y, d);
            acc.z += __shfl_down_sync(0xffffffffu, acc.z, d);
            acc.w += __shfl_down_sync(0xffffffffu, acc.w, d);
        }
        if (sub == 0) g_Yt[(tb >> 2) * KB + bin] = acc;
        __syncthreads();
    }
}

// ---------------------------------------------------------------------------
// K2 (R15 version, byte-identical): replicated+swizzled qm table.
// ---------------------------------------------------------------------------
__global__ void __launch_bounds__(256, 2)
k2_out(const float* __restrict__ qv, const int* __restrict__ assign,
       const float* __restrict__ bias, float* __restrict__ out) {
    __shared__ float4 s_y4[2 * KB];
    __shared__ float4 s_qmp[256];
    __shared__ float4 s_qm4r[KB * 8];

    const int tid = threadIdx.x;
    const int h = tid >> 7, k = tid & 127;
    const int cp = tid & 7;

    float qvr[64];
    #pragma unroll
    for (int i = 0; i < 64; i++)
        qvr[i] = qv[(h * 64 + i) * KB + k];

    float4 biasr[4]; unsigned ar[4];
    #pragma unroll
    for (int i = 0; i < 4; i++) {
        int e4 = i * 256 + tid;
        biasr[i] = ((const float4*)bias)[e4];
        int4 a = ((const int4*)assign)[e4];
        ar[i] = (unsigned)(a.x & 127)
              | ((unsigned)(a.y & 127) << 8)
              | ((unsigned)(a.z & 127) << 16)
              | ((unsigned)(a.w & 127) << 24);
    }

    const int t0 = blockIdx.x * 8;
    s_y4[tid] = g_Yt[(t0 >> 2) * KB + tid];
    __syncthreads();

    float4* out4 = (float4*)out;

    #pragma unroll 1
    for (int g = 0; g < 2; g++) {
        const int tb = t0 + 4 * g;

        unsigned long long acc01 = 0ull, acc23 = 0ull;
        const ulonglong2* sy2 = (const ulonglong2*)(s_y4 + g * KB);
        #pragma unroll
        for (int i = 0; i < 64; i++) {
            unsigned long long qd = pack2(qvr[i]);
            ulonglong2 yv = sy2[h * 64 + i];
            fma2(acc01, yv.x, qd);
            fma2(acc23, yv.y, qd);
        }
        s_qmp[tid] = make_float4(lo2(acc01), hi2(acc01), lo2(acc23), hi2(acc23));
        __syncthreads();
        if (tid < KB) {
            float4 a0 = s_qmp[tid], a1 = s_qmp[tid + 128];
            float4 t = make_float4(a0.x + a1.x, a0.y + a1.y,
                                   a0.z + a1.z, a0.w + a1.w);
            #pragma unroll
            for (int u = 0; u < 8; u++)
                s_qm4r[tid * 8 + ((u + tid) & 7)] = t;
        }
        __syncthreads();

        #pragma unroll
        for (int i = 0; i < 4; i++) {
            unsigned a = ar[i];
            float4 q0 = s_qm4r[(a & 255) * 8 + cp];
            float4 q1 = s_qm4r[((a >> 8)  & 255) * 8 + cp];
            float4 q2 = s_qm4r[((a >> 16) & 255) * 8 + cp];
            float4 q3 = s_qm4r[(a >> 24) * 8 + cp];
            float4 bb = biasr[i];
            size_t rb = (size_t)tb * 1024 + i * 256 + tid;
            out4[rb]        = make_float4(q0.x + bb.x, q1.x + bb.y, q2.x + bb.z, q3.x + bb.w);
            out4[rb + 1024] = make_float4(q0.y + bb.x, q1.y + bb.y, q2.y + bb.z, q3.y + bb.w);
            out4[rb + 2048] = make_float4(q0.z + bb.x, q1.z + bb.y, q2.z + bb.z, q3.z + bb.w);
            out4[rb + 3072] = make_float4(q0.w + bb.x, q1.w + bb.y, q2.w + bb.z, q3.w + bb.w);
        }
        __syncthreads();
    }
}

extern "C" void kernel_launch(void* const* d_in, const int* in_sizes, int n_in,
                              void* d_out, int out_size) {
    const float* x      = (const float*)d_in[0];
    const float* qv     = (const float*)d_in[1];
    const int*   assign = (const int*)d_in[2];
    const float* bias   = (const float*)d_in[3];
    float*       out    = (float*)d_out;

    (void)cudaFuncSetAttribute(k1_bins,
        cudaFuncAttributeMaxDynamicSharedMemorySize, K1_SMEM);

    k0_build<<<KB, 32>>>(assign);
    k1_bins<<<TROWS / 16, 512, K1_SMEM>>>(x);
    k2_out<<<TROWS / 8, 256>>>(qv, assign, bias, out);
}